// round 10
// baseline (speedup 1.0000x reference)
#include <cuda_runtime.h>
#include <cuda_fp16.h>
#include <cstdint>

// Problem constants (fixed by the dataset):
//   N = 50000 nodes, C = 128 channels, E = 400000 edges,
//   T = 12 edge types, P = 16 (4x4 restriction map)
// Y layout per node: [half(src=0/dst=1)][t][p]  -> 2*12*16 = 384 cols
#define NMAX   50000
#define CDIM   128
#define NCOLS  384

// Scratch (allocation-free rule: __device__ globals)
__device__ __half g_Bh[NCOLS * CDIM];                // 96 KB, fp16 W^T: [n][k]
__device__ __half g_Yh[(size_t)NMAX * NCOLS];        // 38.4 MB, fp16 node partials

__device__ __forceinline__ uint32_t smem_u32(const void* p) {
    return (uint32_t)__cvta_generic_to_shared(p);
}
__device__ __forceinline__ uint32_t h2_as_u32(__half2 h) {
    return *reinterpret_cast<uint32_t*>(&h);
}
__device__ __forceinline__ void cp_async16(void* smem_dst, const void* gsrc) {
    asm volatile("cp.async.ca.shared.global [%0], [%1], 16;\n"
                 :: "r"(smem_u32(smem_dst)), "l"(gsrc));
}
#define CP_COMMIT() asm volatile("cp.async.commit_group;\n" ::)
#define CP_WAIT0()  asm volatile("cp.async.wait_group 0;\n" ::)

__device__ __forceinline__ void ldsm_x4(uint32_t& r0, uint32_t& r1,
                                        uint32_t& r2, uint32_t& r3,
                                        uint32_t addr) {
    asm volatile("ldmatrix.sync.aligned.m8n8.x4.shared.b16 {%0,%1,%2,%3}, [%4];"
                 : "=r"(r0), "=r"(r1), "=r"(r2), "=r"(r3) : "r"(addr));
}

__device__ __forceinline__ float fast_tanh(float x) {
    float y;
    asm("tanh.approx.f32 %0, %1;" : "=f"(y) : "f"(x));
    return y;
}

// ---------------------------------------------------------------------------
// Kernel 1: prep. Rearrange W [T,2C,P] -> g_Bh [n=384][k=128] fp16,
// n = half*192 + t*16 + p, k = channel c.
// ---------------------------------------------------------------------------
__global__ void prep_kernel(const float* __restrict__ W) {
    int i = blockIdx.x * blockDim.x + threadIdx.x;   // 0 .. 49151
    int n = i >> 7;           // 0..383
    int k = i & 127;
    int half = n / 192;
    int rem  = n - half * 192;
    int t    = rem >> 4;
    int p    = rem & 15;
    float w = W[((size_t)t * 256 + half * 128 + k) * 16 + p];
    g_Bh[i] = __float2half_rn(w);
}

// ---------------------------------------------------------------------------
// Kernel 2: Y[M,384] = fp16(X[M,128]) @ Bh^T, fp32 accumulate, fp16 out.
// CTA tile 128(M) x 128(N), FULL K=128 resident in smem, single sync.
// 256 threads = 8 warps in 4(M) x 2(N); warp tile 32x64 via mma.m16n8k16.f16.
// Fragments loaded with ldmatrix.x4 (6 LDSM per warp per k16 step instead of
// 24 scalar LDS.32) — relieves the issue pipe so HMMA dispatch dominates.
// Smem rows padded to 136 halves (272 B, stride 68 words == 4 mod 32):
// every 8-row LDSM phase hits distinct 4-bank groups -> conflict-free.
// ---------------------------------------------------------------------------
#define SPAD      136
#define AS_ELEMS  (128 * SPAD)
#define GEMM_SMEM_BYTES (2 * AS_ELEMS * 2)   // 69632 B

__global__ void __launch_bounds__(256, 2)
gemm_kernel(const float* __restrict__ X, int M) {
    extern __shared__ __half smem[];
    __half* As = smem;              // [128][SPAD]  rows = m, cols = k
    __half* Bs = smem + AS_ELEMS;   // [128][SPAD]  rows = n_local, cols = k

    const int m0  = blockIdx.x * 128;
    const int n0  = blockIdx.y * 128;
    const int tid = threadIdx.x;

    // ---- B tile: straight fp16 row copy via cp.async (16 B chunks) ----
    #pragma unroll
    for (int i = 0; i < 8; ++i) {
        int li = tid + i * 256;          // 0..2047
        int r  = li >> 4;                // n_local 0..127
        int c  = (li & 15) << 3;         // k chunk start (8 halves)
        cp_async16(Bs + r * SPAD + c, g_Bh + (size_t)(n0 + r) * CDIM + c);
    }
    CP_COMMIT();

    // ---- A tile: LDG f32x4 -> cvt fp16 -> STS 8 B ----
    #pragma unroll
    for (int i = 0; i < 16; ++i) {
        int li = tid + i * 256;          // 0..4095
        int r  = li >> 5;                // m row 0..127
        int c  = (li & 31) << 2;         // k col (f32 granularity)
        float4 v = make_float4(0.f, 0.f, 0.f, 0.f);
        if (m0 + r < M)
            v = *reinterpret_cast<const float4*>(X + (size_t)(m0 + r) * CDIM + c);
        __half2 h0 = __floats2half2_rn(v.x, v.y);
        __half2 h1 = __floats2half2_rn(v.z, v.w);
        *reinterpret_cast<__half2*>(As + r * SPAD + c)     = h0;
        *reinterpret_cast<__half2*>(As + r * SPAD + c + 2) = h1;
    }
    CP_WAIT0();
    __syncthreads();

    const int warp = tid >> 5;
    const int lane = tid & 31;
    const int wm   = warp >> 1;   // 0..3
    const int wn   = warp & 1;    // 0..1

    float acc[2][8][4];
    #pragma unroll
    for (int mt = 0; mt < 2; ++mt)
        #pragma unroll
        for (int nt = 0; nt < 8; ++nt)
            #pragma unroll
            for (int q = 0; q < 4; ++q)
                acc[mt][nt][q] = 0.f;

    // ldmatrix base addresses (k0 = 0); advance 32 B per k16 step.
    // A, mt in {0,1}: mat = lane>>3: 0=(r+0,k0) 1=(r+8,k0) 2=(r+0,k8) 3=(r+8,k8)
    const int mat = lane >> 3;
    const int mrl = lane & 7;
    uint32_t a_addr[2];
    #pragma unroll
    for (int mt = 0; mt < 2; ++mt) {
        int row = wm * 32 + mt * 16 + (mat & 1) * 8 + mrl;
        int col = (mat >> 1) * 8;
        a_addr[mt] = smem_u32(As + row * SPAD + col);
    }
    // B, group g in {0..3} covers nt = 2g, 2g+1:
    // mat: 0=(nt=2g,k0) 1=(nt=2g,k8) 2=(nt=2g+1,k0) 3=(nt=2g+1,k8)
    uint32_t b_addr[4];
    #pragma unroll
    for (int g = 0; g < 4; ++g) {
        int row = wn * 64 + (2 * g + (mat >> 1)) * 8 + mrl;
        int col = (mat & 1) * 8;
        b_addr[g] = smem_u32(Bs + row * SPAD + col);
    }

    #pragma unroll
    for (int ks = 0; ks < CDIM / 16; ++ks) {  // 8 k16 steps
        const uint32_t koff = ks * 32;        // 16 halves = 32 B
        uint32_t a[2][4];
        #pragma unroll
        for (int mt = 0; mt < 2; ++mt)
            ldsm_x4(a[mt][0], a[mt][1], a[mt][2], a[mt][3], a_addr[mt] + koff);
        uint32_t b[8][2];
        #pragma unroll
        for (int g = 0; g < 4; ++g)
            ldsm_x4(b[2 * g][0], b[2 * g][1], b[2 * g + 1][0], b[2 * g + 1][1],
                    b_addr[g] + koff);
        #pragma unroll
        for (int nt = 0; nt < 8; ++nt) {
            #pragma unroll
            for (int mt = 0; mt < 2; ++mt) {
                asm volatile(
                    "mma.sync.aligned.m16n8k16.row.col.f32.f16.f16.f32 "
                    "{%0,%1,%2,%3}, {%4,%5,%6,%7}, {%8,%9}, {%0,%1,%2,%3};"
                    : "+f"(acc[mt][nt][0]), "+f"(acc[mt][nt][1]),
                      "+f"(acc[mt][nt][2]), "+f"(acc[mt][nt][3])
                    : "r"(a[mt][0]), "r"(a[mt][1]), "r"(a[mt][2]), "r"(a[mt][3]),
                      "r"(b[nt][0]), "r"(b[nt][1]));
            }
        }
    }

    // Epilogue: fp16 half2 stores
    const int grp = lane >> 2;
    const int tig = lane & 3;
    const int rbase = wm * 32 + grp;
    #pragma unroll
    for (int mt = 0; mt < 2; ++mt) {
        int r0 = m0 + rbase + mt * 16;
        #pragma unroll
        for (int nt = 0; nt < 8; ++nt) {
            int cc = n0 + wn * 64 + nt * 8 + tig * 2;
            if (r0 < M) {
                __half2 h = __floats2half2_rn(acc[mt][nt][0], acc[mt][nt][1]);
                *reinterpret_cast<__half2*>(g_Yh + (size_t)r0 * NCOLS + cc) = h;
            }
            if (r0 + 8 < M) {
                __half2 h = __floats2half2_rn(acc[mt][nt][2], acc[mt][nt][3]);
                *reinterpret_cast<__half2*>(g_Yh + (size_t)(r0 + 8) * NCOLS + cc) = h;
            }
        }
    }
}

// ---------------------------------------------------------------------------
// Kernel 3: TWO edges per thread.
// out[e,:16] = tanh(Ysrc[src,t,:] + Ydst[dst,t,:]).
// Vectorized index loads (int2 / longlong2), 8 independent 16 B gathers
// (MLP=8, Y fp16 L2-resident), 128 B fully-coalesced output per thread.
// Index-dtype detect fused per block (edge_types in 0..11: if int64 LE,
// every odd int32 word is 0; false-positive prob on int32 data (1/12)^256).
// ---------------------------------------------------------------------------
__global__ void edge_kernel(const void* __restrict__ ei,
                            const void* __restrict__ et,
                            float* __restrict__ out, int E) {
    const int* etw = (const int*)et;
    int probe = etw[2 * threadIdx.x + 1];
    int idx64 = !__syncthreads_or(probe != 0);

    int p  = blockIdx.x * blockDim.x + threadIdx.x;   // pair id
    int e0 = p * 2;
    if (e0 >= E) return;
    bool has2 = (e0 + 1 < E);

    int s0, s1, d0, d1, t0, t1;
    if (idx64) {
        const longlong2* eis = (const longlong2*)((const long long*)ei + e0);
        const longlong2* eid = (const longlong2*)((const long long*)ei + E + e0);
        const longlong2* ett = (const longlong2*)((const long long*)et + e0);
        longlong2 vs = *eis, vd = *eid, vt = *ett;
        s0 = (int)vs.x; s1 = (int)vs.y;
        d0 = (int)vd.x; d1 = (int)vd.y;
        t0 = (int)vt.x; t1 = (int)vt.y;
    } else {
        const int* ei32 = (const int*)ei;
        int2 vs = *(const int2*)(ei32 + e0);
        int2 vd = *(const int2*)(ei32 + E + e0);
        int2 vt = *(const int2*)(etw + e0);
        s0 = vs.x; s1 = vs.y;
        d0 = vd.x; d1 = vd.y;
        t0 = vt.x; t1 = vt.y;
    }

    // Issue all 8 gathers up front (independent -> high MLP)
    const __half* pa0 = g_Yh + (size_t)s0 * NCOLS + t0 * 16;
    const __half* pb0 = g_Yh + (size_t)d0 * NCOLS + 192 + t0 * 16;
    const __half* pa1 = g_Yh + (size_t)s1 * NCOLS + t1 * 16;
    const __half* pb1 = g_Yh + (size_t)d1 * NCOLS + 192 + t1 * 16;
    uint4 A00 = *reinterpret_cast<const uint4*>(pa0);
    uint4 A01 = *reinterpret_cast<const uint4*>(pa0 + 8);
    uint4 B00 = *reinterpret_cast<const uint4*>(pb0);
    uint4 B01 = *reinterpret_cast<const uint4*>(pb0 + 8);
    uint4 A10, A11, B10, B11;
    if (has2) {
        A10 = *reinterpret_cast<const uint4*>(pa1);
        A11 = *reinterpret_cast<const uint4*>(pa1 + 8);
        B10 = *reinterpret_cast<const uint4*>(pb1);
        B11 = *reinterpret_cast<const uint4*>(pb1 + 8);
    }

    auto emit = [&](uint4 va0, uint4 va1, uint4 vb0, uint4 vb1, float* o) {
        const __half2* a0 = reinterpret_cast<const __half2*>(&va0);
        const __half2* a1 = reinterpret_cast<const __half2*>(&va1);
        const __half2* b0 = reinterpret_cast<const __half2*>(&vb0);
        const __half2* b1 = reinterpret_cast<const __half2*>(&vb1);
        float r[16];
        #pragma unroll
        for (int i = 0; i < 4; ++i) {
            float2 fa = __half22float2(a0[i]);
            float2 fb = __half22float2(b0[i]);
            r[2 * i]     = fast_tanh(fa.x + fb.x);
            r[2 * i + 1] = fast_tanh(fa.y + fb.y);
            float2 ga = __half22float2(a1[i]);
            float2 gb = __half22float2(b1[i]);
            r[8 + 2 * i]     = fast_tanh(ga.x + gb.x);
            r[8 + 2 * i + 1] = fast_tanh(ga.y + gb.y);
        }
        *reinterpret_cast<float4*>(o)      = make_float4(r[0],  r[1],  r[2],  r[3]);
        *reinterpret_cast<float4*>(o + 4)  = make_float4(r[4],  r[5],  r[6],  r[7]);
        *reinterpret_cast<float4*>(o + 8)  = make_float4(r[8],  r[9],  r[10], r[11]);
        *reinterpret_cast<float4*>(o + 12) = make_float4(r[12], r[13], r[14], r[15]);
    };

    emit(A00, A01, B00, B01, out + (size_t)e0 * 16);
    if (has2)
        emit(A10, A11, B10, B11, out + (size_t)(e0 + 1) * 16);
}

// ---------------------------------------------------------------------------
extern "C" void kernel_launch(void* const* d_in, const int* in_sizes, int n_in,
                              void* d_out, int out_size) {
    const float* x  = (const float*)d_in[0];      // [N,128] f32
    const void*  ei = d_in[1];                    // [2,E] int32 or int64
    const void*  et = d_in[2];                    // [E]   int32 or int64
    const float* W  = (const float*)d_in[3];      // [12,256,16] f32

    const int N = in_sizes[0] / CDIM;
    const int E = in_sizes[2];

    // Opt-in >48 KB dynamic smem (immediate host attr set; capture-legal,
    // unconditional -> deterministic).
    cudaFuncSetAttribute(gemm_kernel,
                         cudaFuncAttributeMaxDynamicSharedMemorySize,
                         GEMM_SMEM_BYTES);

    // 1) Weight rearrange/transpose to fp16
    prep_kernel<<<192, 256>>>(W);

    // 2) Dense node-side GEMM: Y = X @ B (fp16 in/out, fp32 accumulate)
    dim3 grid((N + 127) / 128, NCOLS / 128);
    gemm_kernel<<<grid, 256, GEMM_SMEM_BYTES>>>(x, N);

    // 3) Edge gather + add + tanh, 2 edges/thread
    int pairs = (E + 1) / 2;
    edge_kernel<<<(pairs + 255) / 256, 256>>>(ei, et, (float*)d_out, E);
}

// round 11
// speedup vs baseline: 1.0498x; 1.0498x over previous
#include <cuda_runtime.h>
#include <cuda_fp16.h>
#include <cstdint>

// Problem constants (fixed by the dataset):
//   N = 50000 nodes, C = 128 channels, E = 400000 edges,
//   T = 12 edge types, P = 16 (4x4 restriction map)
// Y layout per node: [half(src=0/dst=1)][t][p]  -> 2*12*16 = 384 cols
#define NMAX   50000
#define CDIM   128
#define NCOLS  384

// Scratch (allocation-free rule: __device__ globals)
__device__ __half g_Bh[NCOLS * CDIM];                // 96 KB, fp16 W^T: [n][k]
__device__ __half g_Yh[(size_t)NMAX * NCOLS];        // 38.4 MB, fp16 node partials

__device__ __forceinline__ uint32_t smem_u32(const void* p) {
    return (uint32_t)__cvta_generic_to_shared(p);
}
__device__ __forceinline__ void cp_async16(void* smem_dst, const void* gsrc) {
    asm volatile("cp.async.ca.shared.global [%0], [%1], 16;\n"
                 :: "r"(smem_u32(smem_dst)), "l"(gsrc));
}
#define CP_COMMIT() asm volatile("cp.async.commit_group;\n" ::)
#define CP_WAIT0()  asm volatile("cp.async.wait_group 0;\n" ::)

__device__ __forceinline__ void ldsm_x4(uint32_t& r0, uint32_t& r1,
                                        uint32_t& r2, uint32_t& r3,
                                        uint32_t addr) {
    asm volatile("ldmatrix.sync.aligned.m8n8.x4.shared.b16 {%0,%1,%2,%3}, [%4];"
                 : "=r"(r0), "=r"(r1), "=r"(r2), "=r"(r3) : "r"(addr));
}

__device__ __forceinline__ float fast_tanh(float x) {
    float y;
    asm("tanh.approx.f32 %0, %1;" : "=f"(y) : "f"(x));
    return y;
}

// ---------------------------------------------------------------------------
// Kernel 1: prep — COALESCED READ / scattered write.
// Thread i reads W[i] (perfectly coalesced float stream); decodes
// i = ((t*256 + row)*16 + p), row = half*128 + c; writes fp16 to
// g_Bh[n*128 + c] with n = half*192 + t*16 + p. Scattered 2 B stores are
// fire-and-forget; removes the 64 B-stride gather latency chain (R10 prep
// was 4.0 us at 4% issue = one exposed DRAM round-trip).
// ---------------------------------------------------------------------------
__global__ void prep_kernel(const float* __restrict__ W) {
    int i = blockIdx.x * blockDim.x + threadIdx.x;   // 0 .. 49151
    float w = W[i];
    int p   = i & 15;
    int row = (i >> 4) & 255;
    int t   = i >> 12;
    int half = row >> 7;
    int c    = row & 127;
    int n    = half * 192 + t * 16 + p;
    g_Bh[n * CDIM + c] = __float2half_rn(w);
}

// ---------------------------------------------------------------------------
// Kernel 2: Y[M,384] = fp16(X[M,128]) @ Bh^T, fp32 accumulate, fp16 out.
// CTA tile 128(M) x 128(N), FULL K=128 resident in smem, single sync.
// 256 threads = 8 warps in 4(M) x 2(N); warp tile 32x64 via mma.m16n8k16.f16.
// Fragments via ldmatrix.x4 (6 LDSM per warp per k16 step).
// Smem rows padded to 136 halves (272 B): 8-row LDSM phases land on byte
// offsets {0,16,..,112} mod 128 -> conflict-free.
// ---------------------------------------------------------------------------
#define SPAD      136
#define AS_ELEMS  (128 * SPAD)
#define GEMM_SMEM_BYTES (2 * AS_ELEMS * 2)   // 69632 B

__global__ void __launch_bounds__(256, 2)
gemm_kernel(const float* __restrict__ X, int M) {
    extern __shared__ __half smem[];
    __half* As = smem;              // [128][SPAD]  rows = m, cols = k
    __half* Bs = smem + AS_ELEMS;   // [128][SPAD]  rows = n_local, cols = k

    const int m0  = blockIdx.x * 128;
    const int n0  = blockIdx.y * 128;
    const int tid = threadIdx.x;

    // ---- B tile: straight fp16 row copy via cp.async (16 B chunks) ----
    #pragma unroll
    for (int i = 0; i < 8; ++i) {
        int li = tid + i * 256;          // 0..2047
        int r  = li >> 4;                // n_local 0..127
        int c  = (li & 15) << 3;         // k chunk start (8 halves)
        cp_async16(Bs + r * SPAD + c, g_Bh + (size_t)(n0 + r) * CDIM + c);
    }
    CP_COMMIT();

    // ---- A tile: LDG f32x4 -> cvt fp16 -> STS 8 B ----
    #pragma unroll
    for (int i = 0; i < 16; ++i) {
        int li = tid + i * 256;          // 0..4095
        int r  = li >> 5;                // m row 0..127
        int c  = (li & 31) << 2;         // k col (f32 granularity)
        float4 v = make_float4(0.f, 0.f, 0.f, 0.f);
        if (m0 + r < M)
            v = *reinterpret_cast<const float4*>(X + (size_t)(m0 + r) * CDIM + c);
        __half2 h0 = __floats2half2_rn(v.x, v.y);
        __half2 h1 = __floats2half2_rn(v.z, v.w);
        *reinterpret_cast<__half2*>(As + r * SPAD + c)     = h0;
        *reinterpret_cast<__half2*>(As + r * SPAD + c + 2) = h1;
    }
    CP_WAIT0();
    __syncthreads();

    const int warp = tid >> 5;
    const int lane = tid & 31;
    const int wm   = warp >> 1;   // 0..3
    const int wn   = warp & 1;    // 0..1

    float acc[2][8][4];
    #pragma unroll
    for (int mt = 0; mt < 2; ++mt)
        #pragma unroll
        for (int nt = 0; nt < 8; ++nt)
            #pragma unroll
            for (int q = 0; q < 4; ++q)
                acc[mt][nt][q] = 0.f;

    // ldmatrix base addresses (k0 = 0); advance 32 B per k16 step.
    const int mat = lane >> 3;
    const int mrl = lane & 7;
    uint32_t a_addr[2];
    #pragma unroll
    for (int mt = 0; mt < 2; ++mt) {
        int row = wm * 32 + mt * 16 + (mat & 1) * 8 + mrl;
        int col = (mat >> 1) * 8;
        a_addr[mt] = smem_u32(As + row * SPAD + col);
    }
    uint32_t b_addr[4];
    #pragma unroll
    for (int g = 0; g < 4; ++g) {
        int row = wn * 64 + (2 * g + (mat >> 1)) * 8 + mrl;
        int col = (mat & 1) * 8;
        b_addr[g] = smem_u32(Bs + row * SPAD + col);
    }

    #pragma unroll
    for (int ks = 0; ks < CDIM / 16; ++ks) {  // 8 k16 steps
        const uint32_t koff = ks * 32;        // 16 halves = 32 B
        uint32_t a[2][4];
        #pragma unroll
        for (int mt = 0; mt < 2; ++mt)
            ldsm_x4(a[mt][0], a[mt][1], a[mt][2], a[mt][3], a_addr[mt] + koff);
        uint32_t b[8][2];
        #pragma unroll
        for (int g = 0; g < 4; ++g)
            ldsm_x4(b[2 * g][0], b[2 * g][1], b[2 * g + 1][0], b[2 * g + 1][1],
                    b_addr[g] + koff);
        #pragma unroll
        for (int nt = 0; nt < 8; ++nt) {
            #pragma unroll
            for (int mt = 0; mt < 2; ++mt) {
                asm volatile(
                    "mma.sync.aligned.m16n8k16.row.col.f32.f16.f16.f32 "
                    "{%0,%1,%2,%3}, {%4,%5,%6,%7}, {%8,%9}, {%0,%1,%2,%3};"
                    : "+f"(acc[mt][nt][0]), "+f"(acc[mt][nt][1]),
                      "+f"(acc[mt][nt][2]), "+f"(acc[mt][nt][3])
                    : "r"(a[mt][0]), "r"(a[mt][1]), "r"(a[mt][2]), "r"(a[mt][3]),
                      "r"(b[nt][0]), "r"(b[nt][1]));
            }
        }
    }

    // Epilogue: fp16 half2 stores
    const int grp = lane >> 2;
    const int tig = lane & 3;
    const int rbase = wm * 32 + grp;
    #pragma unroll
    for (int mt = 0; mt < 2; ++mt) {
        int r0 = m0 + rbase + mt * 16;
        #pragma unroll
        for (int nt = 0; nt < 8; ++nt) {
            int cc = n0 + wn * 64 + nt * 8 + tig * 2;
            if (r0 < M) {
                __half2 h = __floats2half2_rn(acc[mt][nt][0], acc[mt][nt][1]);
                *reinterpret_cast<__half2*>(g_Yh + (size_t)r0 * NCOLS + cc) = h;
            }
            if (r0 + 8 < M) {
                __half2 h = __floats2half2_rn(acc[mt][nt][2], acc[mt][nt][3]);
                *reinterpret_cast<__half2*>(g_Yh + (size_t)(r0 + 8) * NCOLS + cc) = h;
            }
        }
    }
}

// ---------------------------------------------------------------------------
// Kernel 3: per edge e, out[e,:16] = tanh(Ysrc[src,t,:] + Ydst[dst,t,:])
// ONE thread per edge (known-good R7 config): 3 index loads + 4 independent
// 16 B gathers (MLP, Y fp16 L2-resident), 16 MUFU tanh.approx, 64 B
// coalesced output. Index-dtype detect fused per block (edge_types in 0..11:
// if int64 LE, every odd int32 word is 0; false-positive prob (1/12)^256).
// ---------------------------------------------------------------------------
__global__ void edge_kernel(const void* __restrict__ ei,
                            const void* __restrict__ et,
                            float* __restrict__ out, int E) {
    const int* etw = (const int*)et;
    int probe = etw[2 * threadIdx.x + 1];
    int idx64 = !__syncthreads_or(probe != 0);

    int e = blockIdx.x * blockDim.x + threadIdx.x;
    if (e >= E) return;

    int src, dst, t;
    if (idx64) {
        const long long* ei64 = (const long long*)ei;
        const long long* et64 = (const long long*)et;
        src = (int)ei64[e];
        dst = (int)ei64[(size_t)E + e];
        t   = (int)et64[e];
    } else {
        const int* ei32 = (const int*)ei;
        src = ei32[e];
        dst = ei32[(size_t)E + e];
        t   = etw[e];
    }

    const __half* pa = g_Yh + (size_t)src * NCOLS + t * 16;
    const __half* pb = g_Yh + (size_t)dst * NCOLS + 192 + t * 16;
    uint4 va0 = *reinterpret_cast<const uint4*>(pa);
    uint4 va1 = *reinterpret_cast<const uint4*>(pa + 8);
    uint4 vb0 = *reinterpret_cast<const uint4*>(pb);
    uint4 vb1 = *reinterpret_cast<const uint4*>(pb + 8);

    const __half2* a0 = reinterpret_cast<const __half2*>(&va0);
    const __half2* a1 = reinterpret_cast<const __half2*>(&va1);
    const __half2* b0 = reinterpret_cast<const __half2*>(&vb0);
    const __half2* b1 = reinterpret_cast<const __half2*>(&vb1);

    float r[16];
    #pragma unroll
    for (int i = 0; i < 4; ++i) {
        float2 fa = __half22float2(a0[i]);
        float2 fb = __half22float2(b0[i]);
        r[2 * i]     = fast_tanh(fa.x + fb.x);
        r[2 * i + 1] = fast_tanh(fa.y + fb.y);
        float2 ga = __half22float2(a1[i]);
        float2 gb = __half22float2(b1[i]);
        r[8 + 2 * i]     = fast_tanh(ga.x + gb.x);
        r[8 + 2 * i + 1] = fast_tanh(ga.y + gb.y);
    }
    float* o = out + (size_t)e * 16;
    *reinterpret_cast<float4*>(o)      = make_float4(r[0],  r[1],  r[2],  r[3]);
    *reinterpret_cast<float4*>(o + 4)  = make_float4(r[4],  r[5],  r[6],  r[7]);
    *reinterpret_cast<float4*>(o + 8)  = make_float4(r[8],  r[9],  r[10], r[11]);
    *reinterpret_cast<float4*>(o + 12) = make_float4(r[12], r[13], r[14], r[15]);
}

// ---------------------------------------------------------------------------
extern "C" void kernel_launch(void* const* d_in, const int* in_sizes, int n_in,
                              void* d_out, int out_size) {
    const float* x  = (const float*)d_in[0];      // [N,128] f32
    const void*  ei = d_in[1];                    // [2,E] int32 or int64
    const void*  et = d_in[2];                    // [E]   int32 or int64
    const float* W  = (const float*)d_in[3];      // [12,256,16] f32

    const int N = in_sizes[0] / CDIM;
    const int E = in_sizes[2];

    // Opt-in >48 KB dynamic smem (immediate host attr set; capture-legal,
    // unconditional -> deterministic).
    cudaFuncSetAttribute(gemm_kernel,
                         cudaFuncAttributeMaxDynamicSharedMemorySize,
                         GEMM_SMEM_BYTES);

    // 1) Weight rearrange/transpose to fp16 (coalesced-read variant)
    prep_kernel<<<192, 256>>>(W);

    // 2) Dense node-side GEMM: Y = X @ B (fp16 in/out, fp32 accumulate)
    dim3 grid((N + 127) / 128, NCOLS / 128);
    gemm_kernel<<<grid, 256, GEMM_SMEM_BYTES>>>(x, N);

    // 3) Edge gather + add + tanh, 1 thread/edge
    edge_kernel<<<(E + 255) / 256, 256>>>(ei, et, (float*)d_out, E);
}